// round 11
// baseline (speedup 1.0000x reference)
#include <cuda_runtime.h>

#define NB 32
#define HH 640
#define WW 640
#define HW (HH * WW)
#define NCHW (NB * 2 * HW)

#define BLK 256
// Late-step 2D tile (round-10 proven): 64 x 8, warp = row, 2 px/thread.
#define TLX 64
#define TLY 8
// Early-step tile: 32 x 8, warp = row, 1 px/thread (shfl neighbor exchange).
#define ETX 32
#define ETY 8
// Steps 1..20 guaranteed tap radius < 1 px (needs max|v| < 12.8 sigma).
#define EARLY_STEPS 20

// Full-field ping-pong scratch, interleaved float2 [N,H,W,(x,y)].
__device__ float2 g_bufA[NB * HW];
__device__ float2 g_bufB[NB * HW];

// ---------------- Blackwell packed f32x2 helpers ----------------
typedef unsigned long long u64;

__device__ __forceinline__ u64 f2bcast(float a) {
    u64 r; asm("mov.b64 %0, {%1, %1};" : "=l"(r) : "f"(a)); return r;
}
__device__ __forceinline__ u64 f2mul(u64 a, u64 b) {
    u64 r; asm("mul.rn.f32x2 %0, %1, %2;" : "=l"(r) : "l"(a), "l"(b)); return r;
}
__device__ __forceinline__ u64 f2add(u64 a, u64 b) {
    u64 r; asm("add.rn.f32x2 %0, %1, %2;" : "=l"(r) : "l"(a), "l"(b)); return r;
}
__device__ __forceinline__ float2 f2unpack(u64 a) {
    float2 v; asm("mov.b64 {%0, %1}, %2;" : "=f"(v.x), "=f"(v.y) : "l"(a)); return v;
}

// Packed bilinear lerp on 4 taps (identical op sequence to round 10).
__device__ __forceinline__ float2 lerp4(u64 v00, u64 v01, u64 v10, u64 v11,
                                        float wx, float wy) {
    u64 wx2 = f2bcast(wx);
    u64 ox2 = f2bcast(1.0f - wx);
    u64 wy2 = f2bcast(wy);
    u64 oy2 = f2bcast(1.0f - wy);
    u64 top = f2add(f2mul(v00, ox2), f2mul(v01, wx2));
    u64 bot = f2add(f2mul(v10, ox2), f2mul(v11, wx2));
    return f2unpack(f2add(f2mul(top, oy2), f2mul(bot, wy2)));
}

// Bilinear sample (border clamp, align_corners=True), gather form (late steps).
__device__ __forceinline__ float2 samp(const float2* __restrict__ b,
                                       float tx, float ty) {
    float px = (tx + 1.0f) * (0.5f * (float)(WW - 1));
    float py = (ty + 1.0f) * (0.5f * (float)(HH - 1));
    px = fminf(fmaxf(px, 0.0f), (float)(WW - 1));
    py = fminf(fmaxf(py, 0.0f), (float)(HH - 1));
    float x0f = floorf(px);
    float y0f = floorf(py);
    int x0 = (int)x0f;
    int y0 = (int)y0f;
    int x1 = min(x0 + 1, WW - 1);
    int y1 = min(y0 + 1, HH - 1);
    float wx = px - x0f;
    float wy = py - y0f;
    const u64* bb = reinterpret_cast<const u64*>(b);
    u64 v00 = bb[y0 * WW + x0];
    u64 v01 = bb[y0 * WW + x1];
    u64 v10 = bb[y1 * WW + x0];
    u64 v11 = bb[y1 * WW + x1];
    return lerp4(v00, v01, v10, v11, wx, wy);
}

// Planar sampler over v with scale S applied to each tap (step 0 only).
__device__ __forceinline__ float2 sampP(const float* __restrict__ vx,
                                        const float* __restrict__ vy,
                                        float tx, float ty, float S) {
    float px = (tx + 1.0f) * (0.5f * (float)(WW - 1));
    float py = (ty + 1.0f) * (0.5f * (float)(HH - 1));
    px = fminf(fmaxf(px, 0.0f), (float)(WW - 1));
    py = fminf(fmaxf(py, 0.0f), (float)(HH - 1));
    float x0f = floorf(px);
    float y0f = floorf(py);
    int x0 = (int)x0f;
    int y0 = (int)y0f;
    int x1 = min(x0 + 1, WW - 1);
    int y1 = min(y0 + 1, HH - 1);
    float wx = px - x0f;
    float wy = py - y0f;
    float sx, sy;
    {
        float a00 = vx[y0 * WW + x0] * S, a01 = vx[y0 * WW + x1] * S;
        float a10 = vx[y1 * WW + x0] * S, a11 = vx[y1 * WW + x1] * S;
        float top = a00 * (1.0f - wx) + a01 * wx;
        float bot = a10 * (1.0f - wx) + a11 * wx;
        sx = top * (1.0f - wy) + bot * wy;
    }
    {
        float a00 = vy[y0 * WW + x0] * S, a01 = vy[y0 * WW + x1] * S;
        float a10 = vy[y1 * WW + x0] * S, a11 = vy[y1 * WW + x1] * S;
        float top = a00 * (1.0f - wx) + a01 * wx;
        float bot = a10 * (1.0f - wx) + a11 * wx;
        sy = top * (1.0f - wy) + bot * wy;
    }
    return make_float2(sx, sy);
}

// ---------- early step: radius<1, row loads + shfl neighbor exchange ----------
// 1 px/thread; warp = one 32-px row. Taps land in cols {x-1,x,x+1} x rows
// {y-1,y,y+1}. Own col loaded for 3 rows; neighbor cols via shfl; lanes 0/31
// fetch their out-of-warp neighbor (with image-border clamp) directly.
// Tap VALUES and lerp ops identical to the gather kernel -> bit-identical.
__global__ __launch_bounds__(BLK, 6) void k_step_e(const float2* __restrict__ src,
                                                   const float2* __restrict__ idg,
                                                   float2* __restrict__ dst) {
    int n = blockIdx.z;
    int y = blockIdx.y * ETY + threadIdx.y;
    int x = blockIdx.x * ETX + threadIdx.x;
    int lane = threadIdx.x;
    int p = y * WW + x;
    const u64* bb = reinterpret_cast<const u64*>(src + (size_t)n * HW);

    int rm = max(y - 1, 0) * WW;
    int rc = y * WW;
    int rp = min(y + 1, HH - 1) * WW;

    u64 c0[3], cm[3], cp[3];
    c0[0] = bb[rm + x];
    c0[1] = bb[rc + x];
    c0[2] = bb[rp + x];

#pragma unroll
    for (int r = 0; r < 3; ++r) {
        cm[r] = __shfl_up_sync(0xffffffffu, c0[r], 1);
        cp[r] = __shfl_down_sync(0xffffffffu, c0[r], 1);
    }
    if (lane == 0) {
        int xm = max(x - 1, 0);
        cm[0] = bb[rm + xm]; cm[1] = bb[rc + xm]; cm[2] = bb[rp + xm];
    }
    if (lane == 31) {
        int xp = min(x + 1, WW - 1);
        cp[0] = bb[rm + xp]; cp[1] = bb[rc + xp]; cp[2] = bb[rp + xp];
    }

    float2 d = f2unpack(c0[1]);
    float2 g = idg[p];

    // Coordinate math identical to samp().
    float tx = g.x + d.x;
    float ty = g.y + d.y;
    float px = (tx + 1.0f) * (0.5f * (float)(WW - 1));
    float py = (ty + 1.0f) * (0.5f * (float)(HH - 1));
    px = fminf(fmaxf(px, 0.0f), (float)(WW - 1));
    py = fminf(fmaxf(py, 0.0f), (float)(HH - 1));
    float x0f = floorf(px);
    float y0f = floorf(py);
    int x0 = (int)x0f;
    int y0 = (int)y0f;
    float wx = px - x0f;
    float wy = py - y0f;

    bool sx = (x0 == x);   // else x0 == x-1 (radius<1 guarantee)
    bool sy = (y0 == y);   // else y0 == y-1

    // Column select per row, then row select. Clamped x1/y1 cases coincide
    // with the clamped cp/row loads (image borders), so values match exactly.
    u64 A0 = sx ? c0[0] : cm[0];
    u64 A1 = sx ? c0[1] : cm[1];
    u64 A2 = sx ? c0[2] : cm[2];
    u64 B0 = sx ? cp[0] : c0[0];
    u64 B1 = sx ? cp[1] : c0[1];
    u64 B2 = sx ? cp[2] : c0[2];

    u64 v00 = sy ? A1 : A0;
    u64 v10 = sy ? A2 : A1;
    u64 v01 = sy ? B1 : B0;
    u64 v11 = sy ? B2 : B1;

    float2 s = lerp4(v00, v01, v10, v11, wx, wy);
    dst[(size_t)n * HW + p] = make_float2(d.x + s.x, d.y + s.y);
}

// ---------- step 0 (round-10 proven) ----------
__global__ __launch_bounds__(BLK, 7) void k_first(const float* __restrict__ v,
                                                  const float2* __restrict__ idg,
                                                  float2* __restrict__ dst) {
    int n = blockIdx.z;
    int y = blockIdx.y * TLY + threadIdx.y;
    int x = blockIdx.x * TLX + threadIdx.x * 2;
    int p = y * WW + x;
    const float* vx = v + (size_t)n * 2 * HW;
    const float* vy = vx + HW;
    const float S = 0x1p-32f;

    float4 g = *reinterpret_cast<const float4*>(idg + p);

    float d0x = vx[p] * S,     d0y = vy[p] * S;
    float d1x = vx[p + 1] * S, d1y = vy[p + 1] * S;

    float2 s0 = sampP(vx, vy, g.x + d0x, g.y + d0y, S);
    float2 s1 = sampP(vx, vy, g.z + d1x, g.w + d1y, S);

    *reinterpret_cast<float4*>(dst + (size_t)n * HW + p) =
        make_float4(d0x + s0.x, d0y + s0.y, d1x + s1.x, d1y + s1.y);
}

// ---------- late steps 21..30 (round-10 proven gather kernel) ----------
__global__ __launch_bounds__(BLK, 7) void k_step(const float2* __restrict__ src,
                                                 const float2* __restrict__ idg,
                                                 float2* __restrict__ dst) {
    int n = blockIdx.z;
    int y = blockIdx.y * TLY + threadIdx.y;
    int x = blockIdx.x * TLX + threadIdx.x * 2;
    int p = y * WW + x;
    const float2* b = src + (size_t)n * HW;

    float4 d = *reinterpret_cast<const float4*>(b + p);
    float4 g = *reinterpret_cast<const float4*>(idg + p);

    float2 s0 = samp(b, g.x + d.x, g.y + d.y);
    float2 s1 = samp(b, g.z + d.z, g.w + d.w);

    *reinterpret_cast<float4*>(dst + (size_t)n * HW + p) =
        make_float4(d.x + s0.x, d.y + s0.y, d.z + s1.x, d.w + s1.y);
}

// ---------- final step + planar output write ----------
__global__ __launch_bounds__(BLK, 7) void k_last(const float2* __restrict__ src,
                                                 const float2* __restrict__ idg,
                                                 float* __restrict__ out) {
    int n = blockIdx.z;
    int y = blockIdx.y * TLY + threadIdx.y;
    int x = blockIdx.x * TLX + threadIdx.x * 2;
    int p = y * WW + x;
    const float2* b = src + (size_t)n * HW;

    float4 d = *reinterpret_cast<const float4*>(b + p);
    float4 g = *reinterpret_cast<const float4*>(idg + p);

    float2 s0 = samp(b, g.x + d.x, g.y + d.y);
    float2 s1 = samp(b, g.z + d.z, g.w + d.w);

    float n0x = d.x + s0.x, n0y = d.y + s0.y;
    float n1x = d.z + s1.x, n1y = d.w + s1.y;

    size_t base = (size_t)n * 2 * HW + p;
    *reinterpret_cast<float2*>(out + base)      = make_float2(g.x + n0x, g.z + n1x);
    *reinterpret_cast<float2*>(out + base + HW) = make_float2(g.y + n0y, g.w + n1y);
    *reinterpret_cast<float2*>(out + NCHW + base)      = make_float2(n0x, n1x);
    *reinterpret_cast<float2*>(out + NCHW + base + HW) = make_float2(n0y, n1y);
}

extern "C" void kernel_launch(void* const* d_in, const int* in_sizes, int n_in,
                              void* d_out, int out_size) {
    const float* v = (const float*)d_in[0];
    const float2* idg = (const float2*)d_in[1];  // [1,H,W,2] interleaved
    float* out = (float*)d_out;

    float2 *A, *B;
    cudaGetSymbolAddress((void**)&A, g_bufA);
    cudaGetSymbolAddress((void**)&B, g_bufB);

    dim3 thr2(32, 8);                         // 2 px/thread kernels
    dim3 blk2(WW / TLX, HH / TLY, NB);        // 10 x 80 x 32
    dim3 thr1(32, 8);                         // 1 px/thread early kernel
    dim3 blk1(WW / ETX, HH / ETY, NB);        // 20 x 80 x 32

    // Step 0 (reads v planar, scale folded) -> A
    k_first<<<blk2, thr2>>>(v, idg, A);

    float2* src = A;
    float2* dst = B;

    // Steps 1..20: shfl/select stencil (radius < 1 guaranteed).
    for (int it = 1; it <= EARLY_STEPS; ++it) {
        k_step_e<<<blk1, thr1>>>(src, idg, dst);
        float2* t = src; src = dst; dst = t;
    }

    // Steps 21..30: gather ping-pong.
    for (int it = EARLY_STEPS + 1; it <= 30; ++it) {
        k_step<<<blk2, thr2>>>(src, idg, dst);
        float2* t = src; src = dst; dst = t;
    }

    // Step 31 fused with planar output write
    k_last<<<blk2, thr2>>>(src, idg, out);
}

// round 12
// speedup vs baseline: 1.2936x; 1.2936x over previous
#include <cuda_runtime.h>

#define NB 32
#define HH 640
#define WW 640
#define HW (HH * WW)
#define NCHW (NB * 2 * HW)

#define CH 16                   // batches per chunk: 2*52MB scratch, L2-resident
#define NCHUNK (NB / CH)

#define BLK 256
// 2D tile per block: 64 px wide x 8 px tall. Warp = one row; lane L handles
// pixels (x0+L) and (x0+L+32) -> every access is lane-consecutive (2 wf, 100%
// line utilization) while keeping 2-sample ILP per thread.
#define TLX 64
#define TLY 8

// Chunk ping-pong scratch, interleaved float2 [CH,H,W,(x,y)].
__device__ float2 g_bufA[CH * HW];
__device__ float2 g_bufB[CH * HW];

// ---------------- Blackwell packed f32x2 helpers ----------------
typedef unsigned long long u64;

__device__ __forceinline__ u64 f2bcast(float a) {
    u64 r; asm("mov.b64 %0, {%1, %1};" : "=l"(r) : "f"(a)); return r;
}
__device__ __forceinline__ u64 f2mul(u64 a, u64 b) {
    u64 r; asm("mul.rn.f32x2 %0, %1, %2;" : "=l"(r) : "l"(a), "l"(b)); return r;
}
__device__ __forceinline__ u64 f2add(u64 a, u64 b) {
    u64 r; asm("add.rn.f32x2 %0, %1, %2;" : "=l"(r) : "l"(a), "l"(b)); return r;
}
__device__ __forceinline__ float2 f2unpack(u64 a) {
    float2 v; asm("mov.b64 {%0, %1}, %2;" : "=f"(v.x), "=f"(v.y) : "l"(a)); return v;
}

// Bilinear sample (border clamp, align_corners=True) from interleaved field
// b[H*W] at normalized coords (tx,ty). Identical arithmetic to rounds 9-10.
__device__ __forceinline__ float2 samp(const float2* __restrict__ b,
                                       float tx, float ty) {
    float px = (tx + 1.0f) * (0.5f * (float)(WW - 1));
    float py = (ty + 1.0f) * (0.5f * (float)(HH - 1));
    px = fminf(fmaxf(px, 0.0f), (float)(WW - 1));
    py = fminf(fmaxf(py, 0.0f), (float)(HH - 1));
    float x0f = floorf(px);
    float y0f = floorf(py);
    int x0 = (int)x0f;
    int y0 = (int)y0f;
    int x1 = min(x0 + 1, WW - 1);
    int y1 = min(y0 + 1, HH - 1);
    float wx = px - x0f;
    float wy = py - y0f;

    const u64* bb = reinterpret_cast<const u64*>(b);
    u64 v00 = bb[y0 * WW + x0];
    u64 v01 = bb[y0 * WW + x1];
    u64 v10 = bb[y1 * WW + x0];
    u64 v11 = bb[y1 * WW + x1];

    u64 wx2 = f2bcast(wx);
    u64 ox2 = f2bcast(1.0f - wx);
    u64 wy2 = f2bcast(wy);
    u64 oy2 = f2bcast(1.0f - wy);

    u64 top = f2add(f2mul(v00, ox2), f2mul(v01, wx2));
    u64 bot = f2add(f2mul(v10, ox2), f2mul(v11, wx2));
    u64 res = f2add(f2mul(top, oy2), f2mul(bot, wy2));
    return f2unpack(res);
}

// Planar sampler over v with scale S applied to each tap (step 0 only).
__device__ __forceinline__ float2 sampP(const float* __restrict__ vx,
                                        const float* __restrict__ vy,
                                        float tx, float ty, float S) {
    float px = (tx + 1.0f) * (0.5f * (float)(WW - 1));
    float py = (ty + 1.0f) * (0.5f * (float)(HH - 1));
    px = fminf(fmaxf(px, 0.0f), (float)(WW - 1));
    py = fminf(fmaxf(py, 0.0f), (float)(HH - 1));
    float x0f = floorf(px);
    float y0f = floorf(py);
    int x0 = (int)x0f;
    int y0 = (int)y0f;
    int x1 = min(x0 + 1, WW - 1);
    int y1 = min(y0 + 1, HH - 1);
    float wx = px - x0f;
    float wy = py - y0f;
    float sx, sy;
    {
        float a00 = vx[y0 * WW + x0] * S, a01 = vx[y0 * WW + x1] * S;
        float a10 = vx[y1 * WW + x0] * S, a11 = vx[y1 * WW + x1] * S;
        float top = a00 * (1.0f - wx) + a01 * wx;
        float bot = a10 * (1.0f - wx) + a11 * wx;
        sx = top * (1.0f - wy) + bot * wy;
    }
    {
        float a00 = vy[y0 * WW + x0] * S, a01 = vy[y0 * WW + x1] * S;
        float a10 = vy[y1 * WW + x0] * S, a11 = vy[y1 * WW + x1] * S;
        float top = a00 * (1.0f - wx) + a01 * wx;
        float bot = a10 * (1.0f - wx) + a11 * wx;
        sy = top * (1.0f - wy) + bot * wy;
    }
    return make_float2(sx, sy);
}

// Mapping (all kernels): block (32,8) -> 64x8 tile; blockIdx=(tx,ty,batch).
// Lane L of warp row handles pixels (x0+L) and (x0+L+32).

// Step 0: disp0 = v*2^-32, one step, write interleaved.
__global__ __launch_bounds__(BLK, 7) void k_first(const float* __restrict__ v,
                                                  const float2* __restrict__ idg,
                                                  float2* __restrict__ dst) {
    int n = blockIdx.z;
    int y = blockIdx.y * TLY + threadIdx.y;
    int x = blockIdx.x * TLX + threadIdx.x;
    int p = y * WW + x;
    const float* vx = v + (size_t)n * 2 * HW;
    const float* vy = vx + HW;
    const float S = 0x1p-32f;

    float2 g0 = idg[p];
    float2 g1 = idg[p + 32];

    float d0x = vx[p] * S,      d0y = vy[p] * S;
    float d1x = vx[p + 32] * S, d1y = vy[p + 32] * S;

    float2 s0 = sampP(vx, vy, g0.x + d0x, g0.y + d0y, S);
    float2 s1 = sampP(vx, vy, g1.x + d1x, g1.y + d1y, S);

    float2* o = dst + (size_t)n * HW;
    o[p]      = make_float2(d0x + s0.x, d0y + s0.y);
    o[p + 32] = make_float2(d1x + s1.x, d1y + s1.y);
}

// Middle steps: interleaved -> interleaved ping-pong, packed-f32x2 lerps.
__global__ __launch_bounds__(BLK, 7) void k_step(const float2* __restrict__ src,
                                                 const float2* __restrict__ idg,
                                                 float2* __restrict__ dst) {
    int n = blockIdx.z;
    int y = blockIdx.y * TLY + threadIdx.y;
    int x = blockIdx.x * TLX + threadIdx.x;
    int p = y * WW + x;
    const float2* b = src + (size_t)n * HW;

    float2 d0 = b[p];
    float2 d1 = b[p + 32];
    float2 g0 = idg[p];
    float2 g1 = idg[p + 32];

    float2 s0 = samp(b, g0.x + d0.x, g0.y + d0.y);
    float2 s1 = samp(b, g1.x + d1.x, g1.y + d1.y);

    float2* o = dst + (size_t)n * HW;
    o[p]      = make_float2(d0.x + s0.x, d0.y + s0.y);
    o[p + 32] = make_float2(d1.x + s1.x, d1.y + s1.y);
}

// Final step: step + planar output write.
//   out[0:NCHW)      = transformation = idgrid + disp
//   out[NCHW:2*NCHW) = displacement
__global__ __launch_bounds__(BLK, 7) void k_last(const float2* __restrict__ src,
                                                 const float2* __restrict__ idg,
                                                 float* __restrict__ out,
                                                 int nglobBase) {
    int n = blockIdx.z;
    int y = blockIdx.y * TLY + threadIdx.y;
    int x = blockIdx.x * TLX + threadIdx.x;
    int p = y * WW + x;
    const float2* b = src + (size_t)n * HW;

    float2 d0 = b[p];
    float2 d1 = b[p + 32];
    float2 g0 = idg[p];
    float2 g1 = idg[p + 32];

    float2 s0 = samp(b, g0.x + d0.x, g0.y + d0.y);
    float2 s1 = samp(b, g1.x + d1.x, g1.y + d1.y);

    float n0x = d0.x + s0.x, n0y = d0.y + s0.y;
    float n1x = d1.x + s1.x, n1y = d1.y + s1.y;

    size_t base = (size_t)(nglobBase + n) * 2 * HW;
    out[base + p]              = g0.x + n0x;   // transformation ch0
    out[base + p + 32]         = g1.x + n1x;
    out[base + HW + p]         = g0.y + n0y;   // transformation ch1
    out[base + HW + p + 32]    = g1.y + n1y;
    out[NCHW + base + p]       = n0x;          // displacement ch0
    out[NCHW + base + p + 32]  = n1x;
    out[NCHW + base + HW + p]  = n0y;          // displacement ch1
    out[NCHW + base + HW + p + 32] = n1y;
}

extern "C" void kernel_launch(void* const* d_in, const int* in_sizes, int n_in,
                              void* d_out, int out_size) {
    const float* v = (const float*)d_in[0];
    const float2* idg = (const float2*)d_in[1];  // [1,H,W,2] interleaved
    float* out = (float*)d_out;

    float2 *A, *B;
    cudaGetSymbolAddress((void**)&A, g_bufA);
    cudaGetSymbolAddress((void**)&B, g_bufB);

    dim3 threads(32, 8);
    dim3 blocks(WW / TLX, HH / TLY, CH);     // 10 x 80 x 16 = 12800 blocks

    for (int c = 0; c < NCHUNK; ++c) {
        const float* vC = v + (size_t)c * CH * 2 * HW;

        // Step 0 (reads v planar, scale folded) -> A
        k_first<<<blocks, threads>>>(vC, idg, A);

        // Steps 1..30 ping-pong within (mostly) L2-resident scratch
        float2* src = A;
        float2* dst = B;
        for (int it = 1; it <= 30; ++it) {
            k_step<<<blocks, threads>>>(src, idg, dst);
            float2* t = src; src = dst; dst = t;
        }
        // After 30 steps result is in src (== A)

        // Step 31 fused with planar output write
        k_last<<<blocks, threads>>>(src, idg, out, c * CH);
    }
}

// round 13
// speedup vs baseline: 1.3926x; 1.0765x over previous
#include <cuda_runtime.h>

#define NB 32
#define HH 640
#define WW 640
#define HW (HH * WW)
#define NCHW (NB * 2 * HW)

#define CH 16                   // batches per chunk: 2*52MB scratch, mostly L2
#define NCHUNK (NB / CH)

#define BLK 256
// 2D tile per block: 128 px wide x 8 px tall. Warp = one row; lane L handles
// pixels x0+L+{0,32,64,96} -> every access lane-consecutive (2 wf, 100% line
// utilization) with 4-sample ILP per thread.
#define TLX 128
#define TLY 8

// Chunk ping-pong scratch, interleaved float2 [CH,H,W,(x,y)].
__device__ float2 g_bufA[CH * HW];
__device__ float2 g_bufB[CH * HW];

// ---------------- Blackwell packed f32x2 helpers ----------------
typedef unsigned long long u64;

__device__ __forceinline__ u64 f2bcast(float a) {
    u64 r; asm("mov.b64 %0, {%1, %1};" : "=l"(r) : "f"(a)); return r;
}
__device__ __forceinline__ u64 f2mul(u64 a, u64 b) {
    u64 r; asm("mul.rn.f32x2 %0, %1, %2;" : "=l"(r) : "l"(a), "l"(b)); return r;
}
__device__ __forceinline__ u64 f2add(u64 a, u64 b) {
    u64 r; asm("add.rn.f32x2 %0, %1, %2;" : "=l"(r) : "l"(a), "l"(b)); return r;
}
__device__ __forceinline__ float2 f2unpack(u64 a) {
    float2 v; asm("mov.b64 {%0, %1}, %2;" : "=f"(v.x), "=f"(v.y) : "l"(a)); return v;
}

// Bilinear sample (border clamp, align_corners=True) from interleaved field
// b[H*W] at normalized coords (tx,ty). Identical arithmetic to rounds 9-12.
__device__ __forceinline__ float2 samp(const float2* __restrict__ b,
                                       float tx, float ty) {
    float px = (tx + 1.0f) * (0.5f * (float)(WW - 1));
    float py = (ty + 1.0f) * (0.5f * (float)(HH - 1));
    px = fminf(fmaxf(px, 0.0f), (float)(WW - 1));
    py = fminf(fmaxf(py, 0.0f), (float)(HH - 1));
    float x0f = floorf(px);
    float y0f = floorf(py);
    int x0 = (int)x0f;
    int y0 = (int)y0f;
    int x1 = min(x0 + 1, WW - 1);
    int y1 = min(y0 + 1, HH - 1);
    float wx = px - x0f;
    float wy = py - y0f;

    const u64* bb = reinterpret_cast<const u64*>(b);
    u64 v00 = bb[y0 * WW + x0];
    u64 v01 = bb[y0 * WW + x1];
    u64 v10 = bb[y1 * WW + x0];
    u64 v11 = bb[y1 * WW + x1];

    u64 wx2 = f2bcast(wx);
    u64 ox2 = f2bcast(1.0f - wx);
    u64 wy2 = f2bcast(wy);
    u64 oy2 = f2bcast(1.0f - wy);

    u64 top = f2add(f2mul(v00, ox2), f2mul(v01, wx2));
    u64 bot = f2add(f2mul(v10, ox2), f2mul(v11, wx2));
    u64 res = f2add(f2mul(top, oy2), f2mul(bot, wy2));
    return f2unpack(res);
}

// Planar sampler over v with scale S applied to each tap (step 0 only).
__device__ __forceinline__ float2 sampP(const float* __restrict__ vx,
                                        const float* __restrict__ vy,
                                        float tx, float ty, float S) {
    float px = (tx + 1.0f) * (0.5f * (float)(WW - 1));
    float py = (ty + 1.0f) * (0.5f * (float)(HH - 1));
    px = fminf(fmaxf(px, 0.0f), (float)(WW - 1));
    py = fminf(fmaxf(py, 0.0f), (float)(HH - 1));
    float x0f = floorf(px);
    float y0f = floorf(py);
    int x0 = (int)x0f;
    int y0 = (int)y0f;
    int x1 = min(x0 + 1, WW - 1);
    int y1 = min(y0 + 1, HH - 1);
    float wx = px - x0f;
    float wy = py - y0f;
    float sx, sy;
    {
        float a00 = vx[y0 * WW + x0] * S, a01 = vx[y0 * WW + x1] * S;
        float a10 = vx[y1 * WW + x0] * S, a11 = vx[y1 * WW + x1] * S;
        float top = a00 * (1.0f - wx) + a01 * wx;
        float bot = a10 * (1.0f - wx) + a11 * wx;
        sx = top * (1.0f - wy) + bot * wy;
    }
    {
        float a00 = vy[y0 * WW + x0] * S, a01 = vy[y0 * WW + x1] * S;
        float a10 = vy[y1 * WW + x0] * S, a11 = vy[y1 * WW + x1] * S;
        float top = a00 * (1.0f - wx) + a01 * wx;
        float bot = a10 * (1.0f - wx) + a11 * wx;
        sy = top * (1.0f - wy) + bot * wy;
    }
    return make_float2(sx, sy);
}

// Step 0: disp0 = v*2^-32, one step, write interleaved.
__global__ __launch_bounds__(BLK, 6) void k_first(const float* __restrict__ v,
                                                  const float2* __restrict__ idg,
                                                  float2* __restrict__ dst) {
    int n = blockIdx.z;
    int y = blockIdx.y * TLY + threadIdx.y;
    int x = blockIdx.x * TLX + threadIdx.x;
    int p = y * WW + x;
    const float* vx = v + (size_t)n * 2 * HW;
    const float* vy = vx + HW;
    const float S = 0x1p-32f;
    float2* o = dst + (size_t)n * HW;

#pragma unroll
    for (int k = 0; k < 4; ++k) {
        int pi = p + k * 32;
        float2 g = idg[pi];
        float dx = vx[pi] * S;
        float dy = vy[pi] * S;
        float2 s = sampP(vx, vy, g.x + dx, g.y + dy, S);
        o[pi] = make_float2(dx + s.x, dy + s.y);
    }
}

// Middle steps: interleaved -> interleaved ping-pong, packed-f32x2 lerps,
// 4 independent samples per thread.
__global__ __launch_bounds__(BLK, 6) void k_step(const float2* __restrict__ src,
                                                 const float2* __restrict__ idg,
                                                 float2* __restrict__ dst) {
    int n = blockIdx.z;
    int y = blockIdx.y * TLY + threadIdx.y;
    int x = blockIdx.x * TLX + threadIdx.x;
    int p = y * WW + x;
    const float2* b = src + (size_t)n * HW;
    float2* o = dst + (size_t)n * HW;

    float2 d[4], g[4];
#pragma unroll
    for (int k = 0; k < 4; ++k) {
        d[k] = b[p + k * 32];
        g[k] = idg[p + k * 32];
    }

    float2 s[4];
#pragma unroll
    for (int k = 0; k < 4; ++k)
        s[k] = samp(b, g[k].x + d[k].x, g[k].y + d[k].y);

#pragma unroll
    for (int k = 0; k < 4; ++k)
        o[p + k * 32] = make_float2(d[k].x + s[k].x, d[k].y + s[k].y);
}

// Final step: step + planar output write.
//   out[0:NCHW)      = transformation = idgrid + disp
//   out[NCHW:2*NCHW) = displacement
__global__ __launch_bounds__(BLK, 6) void k_last(const float2* __restrict__ src,
                                                 const float2* __restrict__ idg,
                                                 float* __restrict__ out,
                                                 int nglobBase) {
    int n = blockIdx.z;
    int y = blockIdx.y * TLY + threadIdx.y;
    int x = blockIdx.x * TLX + threadIdx.x;
    int p = y * WW + x;
    const float2* b = src + (size_t)n * HW;
    size_t base = (size_t)(nglobBase + n) * 2 * HW;

#pragma unroll
    for (int k = 0; k < 4; ++k) {
        int pi = p + k * 32;
        float2 d = b[pi];
        float2 g = idg[pi];
        float2 s = samp(b, g.x + d.x, g.y + d.y);
        float nx = d.x + s.x;
        float ny = d.y + s.y;
        out[base + pi]             = g.x + nx;  // transformation ch0
        out[base + HW + pi]        = g.y + ny;  // transformation ch1
        out[NCHW + base + pi]      = nx;        // displacement ch0
        out[NCHW + base + HW + pi] = ny;        // displacement ch1
    }
}

extern "C" void kernel_launch(void* const* d_in, const int* in_sizes, int n_in,
                              void* d_out, int out_size) {
    const float* v = (const float*)d_in[0];
    const float2* idg = (const float2*)d_in[1];  // [1,H,W,2] interleaved
    float* out = (float*)d_out;

    float2 *A, *B;
    cudaGetSymbolAddress((void**)&A, g_bufA);
    cudaGetSymbolAddress((void**)&B, g_bufB);

    dim3 threads(32, 8);
    dim3 blocks(WW / TLX, HH / TLY, CH);     // 5 x 80 x 16 = 6400 blocks

    for (int c = 0; c < NCHUNK; ++c) {
        const float* vC = v + (size_t)c * CH * 2 * HW;

        // Step 0 (reads v planar, scale folded) -> A
        k_first<<<blocks, threads>>>(vC, idg, A);

        // Steps 1..30 ping-pong within (mostly) L2-resident scratch
        float2* src = A;
        float2* dst = B;
        for (int it = 1; it <= 30; ++it) {
            k_step<<<blocks, threads>>>(src, idg, dst);
            float2* t = src; src = dst; dst = t;
        }
        // After 30 steps result is in src (== A)

        // Step 31 fused with planar output write
        k_last<<<blocks, threads>>>(src, idg, out, c * CH);
    }
}

// round 14
// speedup vs baseline: 1.4406x; 1.0345x over previous
#include <cuda_runtime.h>

#define NB 32
#define HH 640
#define WW 640
#define HW (HH * WW)
#define NCHW (NB * 2 * HW)

#define CH 16                   // batches per chunk: 2*52MB scratch, mostly L2
#define NCHUNK (NB / CH)

#define BLK 256
// 2D tile per block: 128 px wide x 8 px tall. Warp = one row; lane L handles
// pixels x0+L+{0,32,64,96} -> every access lane-consecutive (2 wf, 100% line
// utilization) with 4-sample ILP, computed in two groups of 2 to cap regs.
#define TLX 128
#define TLY 8

// Chunk ping-pong scratch, interleaved float2 [CH,H,W,(x,y)].
__device__ float2 g_bufA[CH * HW];
__device__ float2 g_bufB[CH * HW];

// ---------------- Blackwell packed f32x2 helpers ----------------
typedef unsigned long long u64;

__device__ __forceinline__ u64 f2bcast(float a) {
    u64 r; asm("mov.b64 %0, {%1, %1};" : "=l"(r) : "f"(a)); return r;
}
__device__ __forceinline__ u64 f2mul(u64 a, u64 b) {
    u64 r; asm("mul.rn.f32x2 %0, %1, %2;" : "=l"(r) : "l"(a), "l"(b)); return r;
}
__device__ __forceinline__ u64 f2add(u64 a, u64 b) {
    u64 r; asm("add.rn.f32x2 %0, %1, %2;" : "=l"(r) : "l"(a), "l"(b)); return r;
}
__device__ __forceinline__ float2 f2unpack(u64 a) {
    float2 v; asm("mov.b64 {%0, %1}, %2;" : "=f"(v.x), "=f"(v.y) : "l"(a)); return v;
}

// Bilinear sample (border clamp, align_corners=True) from interleaved field
// b[H*W] at normalized coords (tx,ty). Identical arithmetic to rounds 9-13.
__device__ __forceinline__ float2 samp(const float2* __restrict__ b,
                                       float tx, float ty) {
    float px = (tx + 1.0f) * (0.5f * (float)(WW - 1));
    float py = (ty + 1.0f) * (0.5f * (float)(HH - 1));
    px = fminf(fmaxf(px, 0.0f), (float)(WW - 1));
    py = fminf(fmaxf(py, 0.0f), (float)(HH - 1));
    float x0f = floorf(px);
    float y0f = floorf(py);
    int x0 = (int)x0f;
    int y0 = (int)y0f;
    int x1 = min(x0 + 1, WW - 1);
    int y1 = min(y0 + 1, HH - 1);
    float wx = px - x0f;
    float wy = py - y0f;

    const u64* bb = reinterpret_cast<const u64*>(b);
    u64 v00 = bb[y0 * WW + x0];
    u64 v01 = bb[y0 * WW + x1];
    u64 v10 = bb[y1 * WW + x0];
    u64 v11 = bb[y1 * WW + x1];

    u64 wx2 = f2bcast(wx);
    u64 ox2 = f2bcast(1.0f - wx);
    u64 wy2 = f2bcast(wy);
    u64 oy2 = f2bcast(1.0f - wy);

    u64 top = f2add(f2mul(v00, ox2), f2mul(v01, wx2));
    u64 bot = f2add(f2mul(v10, ox2), f2mul(v11, wx2));
    u64 res = f2add(f2mul(top, oy2), f2mul(bot, wy2));
    return f2unpack(res);
}

// Planar sampler over v with scale S applied to each tap (step 0 only).
__device__ __forceinline__ float2 sampP(const float* __restrict__ vx,
                                        const float* __restrict__ vy,
                                        float tx, float ty, float S) {
    float px = (tx + 1.0f) * (0.5f * (float)(WW - 1));
    float py = (ty + 1.0f) * (0.5f * (float)(HH - 1));
    px = fminf(fmaxf(px, 0.0f), (float)(WW - 1));
    py = fminf(fmaxf(py, 0.0f), (float)(HH - 1));
    float x0f = floorf(px);
    float y0f = floorf(py);
    int x0 = (int)x0f;
    int y0 = (int)y0f;
    int x1 = min(x0 + 1, WW - 1);
    int y1 = min(y0 + 1, HH - 1);
    float wx = px - x0f;
    float wy = py - y0f;
    float sx, sy;
    {
        float a00 = vx[y0 * WW + x0] * S, a01 = vx[y0 * WW + x1] * S;
        float a10 = vx[y1 * WW + x0] * S, a11 = vx[y1 * WW + x1] * S;
        float top = a00 * (1.0f - wx) + a01 * wx;
        float bot = a10 * (1.0f - wx) + a11 * wx;
        sx = top * (1.0f - wy) + bot * wy;
    }
    {
        float a00 = vy[y0 * WW + x0] * S, a01 = vy[y0 * WW + x1] * S;
        float a10 = vy[y1 * WW + x0] * S, a11 = vy[y1 * WW + x1] * S;
        float top = a00 * (1.0f - wx) + a01 * wx;
        float bot = a10 * (1.0f - wx) + a11 * wx;
        sy = top * (1.0f - wy) + bot * wy;
    }
    return make_float2(sx, sy);
}

// Step 0: disp0 = v*2^-32, one step, write interleaved.
__global__ __launch_bounds__(BLK, 7) void k_first(const float* __restrict__ v,
                                                  const float2* __restrict__ idg,
                                                  float2* __restrict__ dst) {
    int n = blockIdx.z;
    int y = blockIdx.y * TLY + threadIdx.y;
    int x = blockIdx.x * TLX + threadIdx.x;
    int p = y * WW + x;
    const float* vx = v + (size_t)n * 2 * HW;
    const float* vy = vx + HW;
    const float S = 0x1p-32f;
    float2* o = dst + (size_t)n * HW;

#pragma unroll
    for (int k = 0; k < 4; ++k) {
        int pi = p + k * 32;
        float2 g = idg[pi];
        float dx = vx[pi] * S;
        float dy = vy[pi] * S;
        float2 s = sampP(vx, vy, g.x + dx, g.y + dy, S);
        o[pi] = make_float2(dx + s.x, dy + s.y);
    }
}

// Middle steps: interleaved -> interleaved ping-pong, packed-f32x2 lerps.
// Loads for all 4 samples batched (first-hop MLP); sampling done in two
// groups of 2 to cap live registers (<=36 -> 7 blocks/SM).
__global__ __launch_bounds__(BLK, 7) void k_step(const float2* __restrict__ src,
                                                 const float2* __restrict__ idg,
                                                 float2* __restrict__ dst) {
    int n = blockIdx.z;
    int y = blockIdx.y * TLY + threadIdx.y;
    int x = blockIdx.x * TLX + threadIdx.x;
    int p = y * WW + x;
    const float2* b = src + (size_t)n * HW;
    float2* o = dst + (size_t)n * HW;

    float2 d[4], g[4];
#pragma unroll
    for (int k = 0; k < 4; ++k) {
        d[k] = b[p + k * 32];
        g[k] = idg[p + k * 32];
    }

    // Group 0: samples 0,1
    {
        float2 s0 = samp(b, g[0].x + d[0].x, g[0].y + d[0].y);
        float2 s1 = samp(b, g[1].x + d[1].x, g[1].y + d[1].y);
        o[p]      = make_float2(d[0].x + s0.x, d[0].y + s0.y);
        o[p + 32] = make_float2(d[1].x + s1.x, d[1].y + s1.y);
    }
    // Group 1: samples 2,3
    {
        float2 s2 = samp(b, g[2].x + d[2].x, g[2].y + d[2].y);
        float2 s3 = samp(b, g[3].x + d[3].x, g[3].y + d[3].y);
        o[p + 64] = make_float2(d[2].x + s2.x, d[2].y + s2.y);
        o[p + 96] = make_float2(d[3].x + s3.x, d[3].y + s3.y);
    }
}

// Final step: step + planar output write.
//   out[0:NCHW)      = transformation = idgrid + disp
//   out[NCHW:2*NCHW) = displacement
__global__ __launch_bounds__(BLK, 7) void k_last(const float2* __restrict__ src,
                                                 const float2* __restrict__ idg,
                                                 float* __restrict__ out,
                                                 int nglobBase) {
    int n = blockIdx.z;
    int y = blockIdx.y * TLY + threadIdx.y;
    int x = blockIdx.x * TLX + threadIdx.x;
    int p = y * WW + x;
    const float2* b = src + (size_t)n * HW;
    size_t base = (size_t)(nglobBase + n) * 2 * HW;

#pragma unroll
    for (int k = 0; k < 4; ++k) {
        int pi = p + k * 32;
        float2 d = b[pi];
        float2 g = idg[pi];
        float2 s = samp(b, g.x + d.x, g.y + d.y);
        float nx = d.x + s.x;
        float ny = d.y + s.y;
        out[base + pi]             = g.x + nx;  // transformation ch0
        out[base + HW + pi]        = g.y + ny;  // transformation ch1
        out[NCHW + base + pi]      = nx;        // displacement ch0
        out[NCHW + base + HW + pi] = ny;        // displacement ch1
    }
}

extern "C" void kernel_launch(void* const* d_in, const int* in_sizes, int n_in,
                              void* d_out, int out_size) {
    const float* v = (const float*)d_in[0];
    const float2* idg = (const float2*)d_in[1];  // [1,H,W,2] interleaved
    float* out = (float*)d_out;

    float2 *A, *B;
    cudaGetSymbolAddress((void**)&A, g_bufA);
    cudaGetSymbolAddress((void**)&B, g_bufB);

    dim3 threads(32, 8);
    dim3 blocks(WW / TLX, HH / TLY, CH);     // 5 x 80 x 16 = 6400 blocks

    for (int c = 0; c < NCHUNK; ++c) {
        const float* vC = v + (size_t)c * CH * 2 * HW;

        // Step 0 (reads v planar, scale folded) -> A
        k_first<<<blocks, threads>>>(vC, idg, A);

        // Steps 1..30 ping-pong within (mostly) L2-resident scratch
        float2* src = A;
        float2* dst = B;
        for (int it = 1; it <= 30; ++it) {
            k_step<<<blocks, threads>>>(src, idg, dst);
            float2* t = src; src = dst; dst = t;
        }
        // After 30 steps result is in src (== A)

        // Step 31 fused with planar output write
        k_last<<<blocks, threads>>>(src, idg, out, c * CH);
    }
}